// round 15
// baseline (speedup 1.0000x reference)
#include <cuda_runtime.h>
#include <math.h>

#define NB   8
#define NC   256
#define LNC  19
#define HH   64
#define WW   64
#define SL   512
#define PIX  (HH*WW)
#define PD   68

typedef unsigned long long ull;

// ---------------- scratch ----------------
static __device__ float    g_mean[NB*NC];
static __device__ float    g_rstd[NB*NC];
static __device__ int      g_labp[NB*PD*PD];
static __device__ float    g_mu[NB*LNC*SL];
static __device__ float    g_muT[512*160];           // [e][bj] tf32-rounded, padded
static __device__ unsigned g_Wsh2[475*256];          // [j*25+i][cpair] bf16x2
static __device__ unsigned g_Wsp2[6400*512];         // [cp*25+d][o2] bf16x2
static __device__ float    g_WgbT[12800*512];        // [d*512+e][o2] tf32-rounded
static __device__ float    g_G[NB*LNC*25*512];
static __device__ unsigned g_G2[NB*LNC*25*256];      // [row][cpair] bf16x2 of G
static __device__ float    g_gavg[NB*PIX*512];       // [b][p][o2]
static __device__ unsigned g_apad2[NB*256*PD*PD];    // [b][cp][y][x] bf16x2; borders stay 0
static __device__ float    g_gsp[NB*512*PIX];        // biases included

// ---------------- helpers ----------------
__device__ __forceinline__ unsigned bf16pack(float lo, float hi) {
    unsigned r;
    asm("cvt.rn.bf16x2.f32 %0, %1, %2;" : "=r"(r) : "f"(hi), "f"(lo));
    return r;
}
__device__ __forceinline__ float tf32r(float x) {
    unsigned u; asm("cvt.rna.tf32.f32 %0, %1;" : "=r"(u) : "f"(x));
    return __uint_as_float(u);
}
__device__ __forceinline__ void mma_bf16(float4& d, const unsigned* a,
                                         unsigned b0, unsigned b1) {
    asm("mma.sync.aligned.m16n8k16.row.col.f32.bf16.bf16.f32 "
        "{%0,%1,%2,%3}, {%4,%5,%6,%7}, {%8,%9}, {%0,%1,%2,%3};"
        : "+f"(d.x), "+f"(d.y), "+f"(d.z), "+f"(d.w)
        : "r"(a[0]), "r"(a[1]), "r"(a[2]), "r"(a[3]), "r"(b0), "r"(b1));
}
__device__ __forceinline__ void mma_tf32(float4& d, const unsigned* a,
                                         unsigned b0, unsigned b1) {
    asm("mma.sync.aligned.m16n8k8.row.col.f32.tf32.tf32.f32 "
        "{%0,%1,%2,%3}, {%4,%5,%6,%7}, {%8,%9}, {%0,%1,%2,%3};"
        : "+f"(d.x), "+f"(d.y), "+f"(d.z), "+f"(d.w)
        : "r"(a[0]), "r"(a[1]), "r"(a[2]), "r"(a[3]), "r"(b0), "r"(b1));
}
__device__ __forceinline__ void cpa16(void* dst, const void* src) {
    unsigned s = (unsigned)__cvta_generic_to_shared(dst);
    asm volatile("cp.async.cg.shared.global [%0], [%1], 16;" :: "r"(s), "l"(src) : "memory");
}
__device__ __forceinline__ void cpa_commit() {
    asm volatile("cp.async.commit_group;" ::: "memory");
}
__device__ __forceinline__ void cpa_wait0() {
    asm volatile("cp.async.wait_group 0;" ::: "memory");
}

// ---------------- instance norm stats ----------------
__global__ void k_stats(const float* __restrict__ x) {
    int bc = blockIdx.x;
    const float* p = x + (size_t)bc * PIX;
    float s = 0.f, ss = 0.f;
    for (int i = threadIdx.x; i < PIX; i += 256) { float v = p[i]; s += v; ss += v * v; }
    __shared__ float sh[512];
    sh[threadIdx.x] = s; sh[256 + threadIdx.x] = ss; __syncthreads();
    for (int off = 128; off > 0; off >>= 1) {
        if (threadIdx.x < off) { sh[threadIdx.x] += sh[threadIdx.x + off]; sh[256 + threadIdx.x] += sh[256 + threadIdx.x + off]; }
        __syncthreads();
    }
    if (threadIdx.x == 0) {
        float m = sh[0] / (float)PIX;
        float v = sh[256] / (float)PIX - m * m;
        g_mean[bc] = m; g_rstd[bc] = rsqrtf(v + 1e-5f);
    }
}

// ---------------- padded label map ----------------
__global__ void k_labels(const float* __restrict__ segmap) {
    int idx = blockIdx.x * 256 + threadIdx.x;
    if (idx >= NB * PD * PD) return;
    int b = idx / (PD * PD), rem = idx % (PD * PD);
    int y = rem / PD, xx = rem % PD;
    int lab = -1;
    if (y >= 2 && y < 66 && xx >= 2 && xx < 66) {
        int h = y - 2, w = xx - 2;
        for (int j = LNC - 1; j >= 0; j--) {
            if (segmap[((b * LNC + j) * HH + h) * WW + w] > 0.f) { lab = j; break; }
        }
    }
    g_labp[idx] = lab;
}

// ---------------- mu ----------------
__global__ void k_mu(const float* __restrict__ style, const float* __restrict__ fc_w,
                     const float* __restrict__ fc_b) {
    int bj = blockIdx.x;
    int b = bj / LNC, j = bj % LNC;
    int tid = threadIdx.x, lane = tid & 31, wid = tid >> 5;
    __shared__ float sc[SL];
    for (int i = tid; i < SL; i += 256) sc[i] = style[(b * LNC + j) * SL + i];
    __syncthreads();
    for (int e = wid; e < SL; e += 8) {
        const float* row = fc_w + ((size_t)(j * SL + e)) * SL;
        float acc = 0.f;
        for (int d = lane; d < SL; d += 32) acc += sc[d] * row[d];
        for (int off = 16; off; off >>= 1) acc += __shfl_xor_sync(0xffffffffu, acc, off);
        if (lane == 0) {
            float v = acc + fc_b[j * SL + e];
            g_mu[(b * LNC + j) * SL + e] = fmaxf(v, 0.f);
        }
    }
}

// ---------------- muT ----------------
__global__ void k_muT() {
    int idx = blockIdx.x * 256 + threadIdx.x;
    if (idx >= 512 * 160) return;
    int e = idx / 160, n = idx % 160;
    g_muT[idx] = (n < 152) ? tf32r(g_mu[n * 512 + e]) : 0.f;
}

// ---------------- tiled transpose (optional tf32 rounding) ----------------
__global__ void k_transpose(const float* __restrict__ in, float* __restrict__ out,
                            int M, int N, int outStride, int colOff, int mode, int rnd) {
    __shared__ float t[32][33];
    int n0 = blockIdx.x * 32, m0 = blockIdx.y * 32;
    int tx = threadIdx.x, ty = threadIdx.y;
    for (int r = ty; r < 32; r += 8) {
        int m = m0 + r, n = n0 + tx;
        t[r][tx] = (m < M && n < N) ? in[(size_t)m * N + n] : 0.f;
    }
    __syncthreads();
    for (int r = ty; r < 32; r += 8) {
        int n = n0 + r, m = m0 + tx;
        if (n < N && m < M) {
            int orow = (mode == 1) ? (n % 25) * 512 + (n / 25) : n;
            float v = t[tx][r];
            if (rnd) v = tf32r(v);
            out[(size_t)orow * outStride + colOff + m] = v;
        }
    }
}

// ---------------- pack spade-shared weights into bf16x2 channel pairs ---------
__global__ void k_wshpack(const float* __restrict__ ssw) {
    int idx = blockIdx.x * 256 + threadIdx.x;
    if (idx >= 475 * 256) return;
    int row = idx >> 8, cp = idx & 255;
    g_Wsh2[idx] = bf16pack(ssw[(2 * cp) * 475 + row], ssw[(2 * cp + 1) * 475 + row]);
}

// ---------------- direct spade-weight transpose+pack ----------------
__global__ void k_wpackd(const float* __restrict__ src, int colOff) {
    __shared__ float t[50][33];
    int cp = blockIdx.x;          // 0..255
    int o0 = blockIdx.y * 32;     // 0..224 step 32
    int tx = threadIdx.x, ty = threadIdx.y;   // 32 x 8
    for (int r = ty; r < 32; r += 8) {
        const float* p = src + (size_t)(o0 + r) * 12800 + cp * 50;
        t[tx][r] = p[tx];
        if (tx < 18) t[32 + tx][r] = p[32 + tx];
    }
    __syncthreads();
    for (int d = ty; d < 25; d += 8) {
        g_Wsp2[(size_t)(cp * 25 + d) * 512 + colOff + o0 + tx] =
            bf16pack(t[d][tx], t[25 + d][tx]);
    }
}

// ---------------- k_G via tf32 MMA: per tap d, G[o2, bj] ----------------
#define AROW 136
#define BROW 168
__global__ void __launch_bounds__(256) k_G_mma() {
    __shared__ float As[2][8 * AROW];
    __shared__ float Bs[2][8 * BROW];
    int d = blockIdx.x, o0 = blockIdx.y * 128;
    int tid = threadIdx.x, lane = tid & 31, wid = tid >> 5;
    int warpM = wid & 1, warpN = wid >> 1;
    int tig = lane & 3, gid = lane >> 2;
    const float* Wd = g_WgbT + (size_t)d * 512 * 512;

    auto loadA = [&](int buf, int k0) {
        int r = tid >> 5, c = tid & 31;
        cpa16(&As[buf][r * AROW + c * 4], Wd + (size_t)(k0 + r) * 512 + o0 + c * 4);
    };
    auto loadB = [&](int buf, int k0) {
        for (int i = tid; i < 320; i += 256) {
            int r = i / 40, c = i % 40;
            cpa16(&Bs[buf][r * BROW + c * 4], g_muT + (k0 + r) * 160 + c * 4);
        }
    };
    loadA(0, 0); loadB(0, 0); cpa_commit();

    float4 acc[4][5];
    #pragma unroll
    for (int mt = 0; mt < 4; mt++)
        #pragma unroll
        for (int nt = 0; nt < 5; nt++) acc[mt][nt] = make_float4(0.f, 0.f, 0.f, 0.f);

    cpa_wait0();
    __syncthreads();

    for (int kc = 0; kc < 64; kc++) {
        int buf = kc & 1;
        if (kc < 63) { loadA(buf ^ 1, (kc + 1) * 8); loadB(buf ^ 1, (kc + 1) * 8); }
        cpa_commit();
        const float* ap = &As[buf][tig * AROW + warpM * 64 + gid];
        const float* bp = &Bs[buf][tig * BROW + warpN * 40 + gid];
        unsigned a[4][4];
        #pragma unroll
        for (int mt = 0; mt < 4; mt++) {
            const float* p0 = ap + mt * 16;
            a[mt][0] = __float_as_uint(p0[0]);
            a[mt][1] = __float_as_uint(p0[8]);
            a[mt][2] = __float_as_uint(p0[4 * AROW]);
            a[mt][3] = __float_as_uint(p0[4 * AROW + 8]);
        }
        #pragma unroll
        for (int nt = 0; nt < 5; nt++) {
            unsigned b0 = __float_as_uint(bp[nt * 8]);
            unsigned b1 = __float_as_uint(bp[nt * 8 + 4 * BROW]);
            #pragma unroll
            for (int mt = 0; mt < 4; mt++)
                mma_tf32(acc[mt][nt], a[mt], b0, b1);
        }
        cpa_wait0();
        __syncthreads();
    }

    #pragma unroll
    for (int mt = 0; mt < 4; mt++) {
        int m = o0 + warpM * 64 + mt * 16 + gid;
        #pragma unroll
        for (int nt = 0; nt < 5; nt++) {
            int n = warpN * 40 + nt * 8 + tig * 2;
            if (n < 152) {
                g_G[((size_t)(n * 25 + d)) * 512 + m] = acc[mt][nt].x;
                g_G[((size_t)(n * 25 + d)) * 512 + m + 8] = acc[mt][nt].z;
            }
            if (n + 1 < 152) {
                g_G[((size_t)((n + 1) * 25 + d)) * 512 + m] = acc[mt][nt].y;
                g_G[((size_t)((n + 1) * 25 + d)) * 512 + m + 8] = acc[mt][nt].w;
            }
        }
    }
}

// ---------------- pack G into bf16x2 channel pairs ----------------
__global__ void k_gpack() {
    int idx = blockIdx.x * 256 + threadIdx.x;
    if (idx >= NB * LNC * 25 * 256) return;
    int row = idx >> 8, cp = idx & 255;
    float2 v = ((const float2*)(g_G + (size_t)row * 512))[cp];
    g_G2[idx] = bf16pack(v.x, v.y);
}

// ---------------- fused gather (gavg) + actv -> apad2 direct ----------------
// tid = channel pair cp (0..255). Reads bf16x2 G2/Wsh2 tables; accumulates fp32.
__global__ void k_gact(const float* __restrict__ sh_b) {
    int bh = blockIdx.x;
    int b = bh >> 6, h = bh & 63;
    int tid = threadIdx.x;
    __shared__ int labw[5 * PD];
    for (int i = tid; i < 5 * PD; i += 256)
        labw[i] = g_labp[(b * PD + h + i / PD) * PD + (i % PD)];
    __syncthreads();
    float2 bias = ((const float2*)sh_b)[tid];
    unsigned* apadRow = g_apad2 + ((size_t)(b * 256 + tid) * PD + (h + 2)) * PD + 2;
    for (int w = 0; w < WW; w++) {
        float g0 = 0.f, g1 = 0.f, a0 = bias.x, a1 = bias.y;
        #pragma unroll
        for (int i = 0; i < 25; i++) {
            int j = labw[(i / 5) * PD + w + (i % 5)];
            if (j >= 0) {
                unsigned gv = g_G2[((b * LNC + j) * 25 + i) * 256 + tid];
                unsigned wv = g_Wsh2[(j * 25 + i) * 256 + tid];
                g0 += __uint_as_float(gv << 16);
                g1 += __uint_as_float(gv & 0xffff0000u);
                a0 += __uint_as_float(wv << 16);
                a1 += __uint_as_float(wv & 0xffff0000u);
            }
        }
        ((float2*)(g_gavg + ((size_t)(b * PIX + h * WW + w)) * 512))[tid] = make_float2(g0, g1);
        apadRow[w] = bf16pack(fmaxf(a0, 0.f), fmaxf(a1, 0.f));
    }
}

// ---------------- spade conv via mma.sync bf16 m16n8k16 (R10/R13 config) ------
#define PLA   552
#define WROW  136
#define WTILE (8*WROW)
#define WKY   (5*WTILE)
#define ASBUF (8*PLA)
#define SMEMB ((2*ASBUF + 2*WKY)*4)

__global__ void __launch_bounds__(256, 1)
k_conv_mma(const float* __restrict__ sgb, const float* __restrict__ sbb) {
    extern __shared__ unsigned sm[];
    unsigned* Asm = sm;
    unsigned* Wsm = sm + 2 * ASBUF;

    const int o0 = blockIdx.x * 128;
    const int h0 = blockIdx.y * 4;
    const int b  = blockIdx.z;
    const int tid = threadIdx.x;
    const int lane = tid & 31, wid = tid >> 5;
    const int warpM = wid & 1;
    const int warpN = wid >> 1;
    const int tig = lane & 3, gid = lane >> 2;

    const unsigned* apadB = g_apad2 + (size_t)b * 256 * PD * PD;

    auto loadWs = [&](int r, int cp0, int ky) {
        #pragma unroll
        for (int ii = 0; ii < 5; ii++) {
            int i = ii * 256 + tid;
            int kx = i >> 8, rem = i & 255;
            int kc = rem >> 5, c4 = rem & 31;
            cpa16(Wsm + r * WKY + kx * WTILE + kc * WROW + c4 * 4,
                  g_Wsp2 + ((size_t)((cp0 + kc) * 25 + ky * 5 + kx)) * 512 + o0 + c4 * 4);
        }
    };
    auto loadAs = [&](int abf, int cp0) {
        for (int i = tid; i < 1088; i += 256) {
            int pl = i / 136, rem = i % 136;
            int row = rem / 17, c4 = rem % 17;
            cpa16(Asm + abf * ASBUF + pl * PLA + row * 68 + c4 * 4,
                  apadB + ((size_t)(cp0 + pl) * PD + (h0 + row)) * PD + c4 * 4);
        }
    };

    loadAs(0, 0);
    loadWs(0, 0, 0);
    cpa_commit();

    const int mrow = o0 + warpM * 64 + gid;
    float4 acc[4][8];
    #pragma unroll
    for (int mt = 0; mt < 4; mt++) {
        int r0 = mrow + mt * 16;
        float bx = (r0 < 256) ? sgb[r0] : sbb[r0 - 256];
        int r8 = r0 + 8;
        float bz = (r8 < 256) ? sgb[r8] : sbb[r8 - 256];
        #pragma unroll
        for (int nt = 0; nt < 8; nt++) acc[mt][nt] = make_float4(bx, bx, bz, bz);
    }

    cpa_wait0();
    __syncthreads();

    const int aoff = warpM * 64 + gid;

    for (int cc = 0; cc < 32; cc++) {
        int cp0 = cc * 8;
        int abuf = cc & 1;
        #pragma unroll 1
        for (int ky = 0; ky < 5; ky++) {
            int wbuf = (cc * 5 + ky) & 1;
            int kyn = ky + 1, ccn = cc, cp0n = cp0;
            if (kyn == 5) { kyn = 0; ccn = cc + 1; cp0n = cp0 + 8; }
            if (ccn < 32) {
                loadWs(wbuf ^ 1, cp0n, kyn);
                if (kyn == 0) loadAs(abuf ^ 1, cp0n);
            }
            cpa_commit();

            const unsigned* wk = Wsm + wbuf * WKY;
            const unsigned* bbase = Asm + abuf * ASBUF + tig * PLA
                                  + (warpN + ky) * 68 + gid;
            #pragma unroll
            for (int kx = 0; kx < 5; kx++) {
                unsigned a[4][4];
                #pragma unroll
                for (int mt = 0; mt < 4; mt++) {
                    const unsigned* p0 = wk + kx * WTILE + tig * WROW + aoff + mt * 16;
                    a[mt][0] = p0[0];
                    a[mt][1] = p0[8];
                    a[mt][2] = p0[4 * WROW];
                    a[mt][3] = p0[4 * WROW + 8];
                }
                const unsigned* bp = bbase + kx;
                #pragma unroll
                for (int nt = 0; nt < 8; nt++) {
                    unsigned b0 = bp[nt * 8];
                    unsigned b1 = bp[nt * 8 + 4 * PLA];
                    #pragma unroll
                    for (int mt = 0; mt < 4; mt++)
                        mma_bf16(acc[mt][nt], a[mt], b0, b1);
                }
            }
            cpa_wait0();
            __syncthreads();
        }
    }

    #pragma unroll
    for (int mt = 0; mt < 4; mt++) {
        int r0 = mrow + mt * 16;
        size_t base0 = (((size_t)b * 512 + r0) * HH + (h0 + warpN)) * WW;
        size_t base1 = (((size_t)b * 512 + r0 + 8) * HH + (h0 + warpN)) * WW;
        #pragma unroll
        for (int nt = 0; nt < 8; nt++) {
            int w = nt * 8 + tig * 2;
            *(float2*)&g_gsp[base0 + w] = make_float2(acc[mt][nt].x, acc[mt][nt].y);
            *(float2*)&g_gsp[base1 + w] = make_float2(acc[mt][nt].z, acc[mt][nt].w);
        }
    }
}

// ---------------- final blend (smem-transposed gavg reads) ----------------
__global__ void __launch_bounds__(256) k_final(const float* __restrict__ x,
                        const float* __restrict__ cgb, const float* __restrict__ cbb,
                        const float* __restrict__ bg, const float* __restrict__ bb,
                        float* __restrict__ out) {
    __shared__ float tsg[64][65];
    __shared__ float tsb[64][65];
    int bh = blockIdx.x;
    int b = bh >> 6, h = bh & 63;
    int tid = threadIdx.x;
    int w = tid & 63, os = tid >> 6;
    float ga = 1.f / (1.f + expf(-bg[0]));
    float ba = 1.f / (1.f + expf(-bb[0]));

    int lw0 = tid >> 4;
    int j4 = (tid & 15) * 4;

    for (int oc0 = 0; oc0 < 256; oc0 += 64) {
        float4 bg4 = *(const float4*)&cgb[oc0 + j4];
        float4 bb4 = *(const float4*)&cbb[oc0 + j4];
        #pragma unroll
        for (int it = 0; it < 4; it++) {
            int lw = lw0 + it * 16;
            size_t pbase = ((size_t)(b * PIX + h * WW + lw)) * 512;
            float4 vg = *(const float4*)&g_gavg[pbase + oc0 + j4];
            float4 vb = *(const float4*)&g_gavg[pbase + 256 + oc0 + j4];
            tsg[lw][j4 + 0] = vg.x + bg4.x;
            tsg[lw][j4 + 1] = vg.y + bg4.y;
            tsg[lw][j4 + 2] = vg.z + bg4.z;
            tsg[lw][j4 + 3] = vg.w + bg4.w;
            tsb[lw][j4 + 0] = vb.x + bb4.x;
            tsb[lw][j4 + 1] = vb.y + bb4.y;
            tsb[lw][j4 + 2] = vb.z + bb4.z;
            tsb[lw][j4 + 3] = vb.w + bb4.w;
        }
        __syncthreads();
        for (int oo = 0; oo < 64; oo += 4) {
            int o = oc0 + oo + os;
            float m = g_mean[b * NC + o], rs = g_rstd[b * NC + o];
            size_t xi = ((size_t)(b * NC + o) * HH + h) * WW + w;
            float nv = (x[xi] - m) * rs;
            float gs = g_gsp[((size_t)(b * 512 + o) * HH + h) * WW + w];
            float bs = g_gsp[((size_t)(b * 512 + o + 256) * HH + h) * WW + w];
            float gav = tsg[w][oo + os];
            float bav = tsb[w][oo + os];
            float gf = ga * gav + (1.f - ga) * gs;
            float bf = ba * bav + (1.f - ba) * bs;
            out[xi] = nv * (1.f + gf) + bf;
        }
        __syncthreads();
    }
}

// ---------------- launch ----------------
extern "C" void kernel_launch(void* const* d_in, const int* in_sizes, int n_in,
                              void* d_out, int out_size) {
    const float* x      = (const float*)d_in[0];
    const float* segmap = (const float*)d_in[1];
    const float* style  = (const float*)d_in[2];
    const float* fc_w   = (const float*)d_in[3];
    const float* fc_b   = (const float*)d_in[4];
    const float* cgw    = (const float*)d_in[5];
    const float* cgb    = (const float*)d_in[6];
    const float* cbw    = (const float*)d_in[7];
    const float* cbb    = (const float*)d_in[8];
    const float* ssw    = (const float*)d_in[9];
    const float* ssb    = (const float*)d_in[10];
    const float* sgw    = (const float*)d_in[11];
    const float* sgb    = (const float*)d_in[12];
    const float* sbw    = (const float*)d_in[13];
    const float* sbb    = (const float*)d_in[14];
    const float* bg     = (const float*)d_in[15];
    const float* bb     = (const float*)d_in[16];
    float* out = (float*)d_out;

    float* pWgbT; cudaGetSymbolAddress((void**)&pWgbT, g_WgbT);

    cudaFuncSetAttribute(k_conv_mma, cudaFuncAttributeMaxDynamicSharedMemorySize, SMEMB);

    dim3 tb(32, 8);

    k_stats<<<NB * NC, 256>>>(x);
    k_labels<<<(NB * PD * PD + 255) / 256, 256>>>(segmap);
    k_mu<<<NB * LNC, 256>>>(style, fc_w, fc_b);
    k_muT<<<(512 * 160 + 255) / 256, 256>>>();

    k_wshpack<<<(475 * 256 + 255) / 256, 256>>>(ssw);
    k_wpackd<<<dim3(256, 8), tb>>>(sgw, 0);
    k_wpackd<<<dim3(256, 8), tb>>>(sbw, 256);
    k_transpose<<<dim3(400, 8), tb>>>(cgw, pWgbT, 256, 12800, 512, 0, 1, 1);
    k_transpose<<<dim3(400, 8), tb>>>(cbw, pWgbT, 256, 12800, 512, 256, 1, 1);

    k_G_mma<<<dim3(25, 4), 256>>>();
    k_gpack<<<(NB * LNC * 25 * 256 + 255) / 256, 256>>>();
    k_gact<<<NB * HH, 256>>>(ssb);
    k_conv_mma<<<dim3(4, 16, NB), 256, SMEMB>>>(sgb, sbb);
    k_final<<<NB * HH, 256>>>(x, cgb, cbb, bg, bb, out);
}

// round 16
// speedup vs baseline: 1.0476x; 1.0476x over previous
#include <cuda_runtime.h>
#include <math.h>

#define NB   8
#define NC   256
#define LNC  19
#define HH   64
#define WW   64
#define SL   512
#define PIX  (HH*WW)
#define PD   68

typedef unsigned long long ull;

// ---------------- scratch ----------------
static __device__ float    g_mean[NB*NC];
static __device__ float    g_rstd[NB*NC];
static __device__ int      g_labp[NB*PD*PD];
static __device__ float    g_mu[NB*LNC*SL];
static __device__ float    g_muT[512*160];           // [e][bj] tf32-rounded, padded
static __device__ unsigned g_Wsh2[475*256];          // [j*25+i][cpair] bf16x2
static __device__ unsigned g_Wsp2[6400*512];         // [cp*25+d][o2] bf16x2
static __device__ float    g_WgbT[12800*512];        // [d*512+e][o2] tf32-rounded
static __device__ float    g_G[NB*LNC*25*512];
static __device__ float    g_gavg[NB*PIX*512];       // [b][p][o2]
static __device__ unsigned g_apad2[NB*256*PD*PD];    // [b][cp][y][x] bf16x2; borders stay 0
static __device__ float    g_gsp[NB*512*PIX];        // biases included

// ---------------- helpers ----------------
__device__ __forceinline__ unsigned bf16pack(float lo, float hi) {
    unsigned r;
    asm("cvt.rn.bf16x2.f32 %0, %1, %2;" : "=r"(r) : "f"(hi), "f"(lo));
    return r;
}
__device__ __forceinline__ float tf32r(float x) {
    unsigned u; asm("cvt.rna.tf32.f32 %0, %1;" : "=r"(u) : "f"(x));
    return __uint_as_float(u);
}
__device__ __forceinline__ void mma_bf16(float4& d, const unsigned* a,
                                         unsigned b0, unsigned b1) {
    asm("mma.sync.aligned.m16n8k16.row.col.f32.bf16.bf16.f32 "
        "{%0,%1,%2,%3}, {%4,%5,%6,%7}, {%8,%9}, {%0,%1,%2,%3};"
        : "+f"(d.x), "+f"(d.y), "+f"(d.z), "+f"(d.w)
        : "r"(a[0]), "r"(a[1]), "r"(a[2]), "r"(a[3]), "r"(b0), "r"(b1));
}
__device__ __forceinline__ void mma_tf32(float4& d, const unsigned* a,
                                         unsigned b0, unsigned b1) {
    asm("mma.sync.aligned.m16n8k8.row.col.f32.tf32.tf32.f32 "
        "{%0,%1,%2,%3}, {%4,%5,%6,%7}, {%8,%9}, {%0,%1,%2,%3};"
        : "+f"(d.x), "+f"(d.y), "+f"(d.z), "+f"(d.w)
        : "r"(a[0]), "r"(a[1]), "r"(a[2]), "r"(a[3]), "r"(b0), "r"(b1));
}
__device__ __forceinline__ void cpa16(void* dst, const void* src) {
    unsigned s = (unsigned)__cvta_generic_to_shared(dst);
    asm volatile("cp.async.cg.shared.global [%0], [%1], 16;" :: "r"(s), "l"(src) : "memory");
}
__device__ __forceinline__ void cpa_commit() {
    asm volatile("cp.async.commit_group;" ::: "memory");
}
__device__ __forceinline__ void cpa_wait0() {
    asm volatile("cp.async.wait_group 0;" ::: "memory");
}

// ---------------- instance norm stats ----------------
__global__ void k_stats(const float* __restrict__ x) {
    int bc = blockIdx.x;
    const float* p = x + (size_t)bc * PIX;
    float s = 0.f, ss = 0.f;
    for (int i = threadIdx.x; i < PIX; i += 256) { float v = p[i]; s += v; ss += v * v; }
    __shared__ float sh[512];
    sh[threadIdx.x] = s; sh[256 + threadIdx.x] = ss; __syncthreads();
    for (int off = 128; off > 0; off >>= 1) {
        if (threadIdx.x < off) { sh[threadIdx.x] += sh[threadIdx.x + off]; sh[256 + threadIdx.x] += sh[256 + threadIdx.x + off]; }
        __syncthreads();
    }
    if (threadIdx.x == 0) {
        float m = sh[0] / (float)PIX;
        float v = sh[256] / (float)PIX - m * m;
        g_mean[bc] = m; g_rstd[bc] = rsqrtf(v + 1e-5f);
    }
}

// ---------------- padded label map ----------------
__global__ void k_labels(const float* __restrict__ segmap) {
    int idx = blockIdx.x * 256 + threadIdx.x;
    if (idx >= NB * PD * PD) return;
    int b = idx / (PD * PD), rem = idx % (PD * PD);
    int y = rem / PD, xx = rem % PD;
    int lab = -1;
    if (y >= 2 && y < 66 && xx >= 2 && xx < 66) {
        int h = y - 2, w = xx - 2;
        for (int j = LNC - 1; j >= 0; j--) {
            if (segmap[((b * LNC + j) * HH + h) * WW + w] > 0.f) { lab = j; break; }
        }
    }
    g_labp[idx] = lab;
}

// ---------------- mu (also writes tf32-rounded transposed muT) ----------------
__global__ void k_mu(const float* __restrict__ style, const float* __restrict__ fc_w,
                     const float* __restrict__ fc_b) {
    int bj = blockIdx.x;                 // 0..151
    int b = bj / LNC, j = bj % LNC;
    int tid = threadIdx.x, lane = tid & 31, wid = tid >> 5;
    __shared__ float sc[SL];
    for (int i = tid; i < SL; i += 256) sc[i] = style[(b * LNC + j) * SL + i];
    __syncthreads();
    for (int e = wid; e < SL; e += 8) {
        const float* row = fc_w + ((size_t)(j * SL + e)) * SL;
        float acc = 0.f;
        for (int d = lane; d < SL; d += 32) acc += sc[d] * row[d];
        for (int off = 16; off; off >>= 1) acc += __shfl_xor_sync(0xffffffffu, acc, off);
        if (lane == 0) {
            float v = fmaxf(acc + fc_b[j * SL + e], 0.f);
            g_mu[(b * LNC + j) * SL + e] = v;
            g_muT[e * 160 + bj] = tf32r(v);
        }
    }
}

// zero muT pad columns 152..159 (one-time tiny kernel; deterministic every call)
__global__ void k_muTpad() {
    int idx = blockIdx.x * 256 + threadIdx.x;
    if (idx >= 512 * 8) return;
    g_muT[(idx >> 3) * 160 + 152 + (idx & 7)] = 0.f;
}

// ---------------- tiled transpose (optional tf32 rounding) ----------------
__global__ void k_transpose(const float* __restrict__ in, float* __restrict__ out,
                            int M, int N, int outStride, int colOff, int mode, int rnd) {
    __shared__ float t[32][33];
    int n0 = blockIdx.x * 32, m0 = blockIdx.y * 32;
    int tx = threadIdx.x, ty = threadIdx.y;
    for (int r = ty; r < 32; r += 8) {
        int m = m0 + r, n = n0 + tx;
        t[r][tx] = (m < M && n < N) ? in[(size_t)m * N + n] : 0.f;
    }
    __syncthreads();
    for (int r = ty; r < 32; r += 8) {
        int n = n0 + r, m = m0 + tx;
        if (n < N && m < M) {
            int orow = (mode == 1) ? (n % 25) * 512 + (n / 25) : n;
            float v = t[tx][r];
            if (rnd) v = tf32r(v);
            out[(size_t)orow * outStride + colOff + m] = v;
        }
    }
}

// ---------------- pack spade-shared weights into bf16x2 channel pairs ---------
__global__ void k_wshpack(const float* __restrict__ ssw) {
    int idx = blockIdx.x * 256 + threadIdx.x;
    if (idx >= 475 * 256) return;
    int row = idx >> 8, cp = idx & 255;
    g_Wsh2[idx] = bf16pack(ssw[(2 * cp) * 475 + row], ssw[(2 * cp + 1) * 475 + row]);
}

// ---------------- direct spade-weight transpose+pack ----------------
__global__ void k_wpackd(const float* __restrict__ src, int colOff) {
    __shared__ float t[50][33];
    int cp = blockIdx.x;          // 0..255
    int o0 = blockIdx.y * 32;     // 0..224 step 32
    int tx = threadIdx.x, ty = threadIdx.y;   // 32 x 8
    for (int r = ty; r < 32; r += 8) {
        const float* p = src + (size_t)(o0 + r) * 12800 + cp * 50;
        t[tx][r] = p[tx];
        if (tx < 18) t[32 + tx][r] = p[32 + tx];
    }
    __syncthreads();
    for (int d = ty; d < 25; d += 8) {
        g_Wsp2[(size_t)(cp * 25 + d) * 512 + colOff + o0 + tx] =
            bf16pack(t[d][tx], t[25 + d][tx]);
    }
}

// ---------------- k_G via tf32 MMA: per tap d, G[o2, bj] ----------------
#define AROW 136
#define BROW 168
__global__ void __launch_bounds__(256) k_G_mma() {
    __shared__ float As[2][8 * AROW];
    __shared__ float Bs[2][8 * BROW];
    int d = blockIdx.x, o0 = blockIdx.y * 128;
    int tid = threadIdx.x, lane = tid & 31, wid = tid >> 5;
    int warpM = wid & 1, warpN = wid >> 1;
    int tig = lane & 3, gid = lane >> 2;
    const float* Wd = g_WgbT + (size_t)d * 512 * 512;

    auto loadA = [&](int buf, int k0) {
        int r = tid >> 5, c = tid & 31;
        cpa16(&As[buf][r * AROW + c * 4], Wd + (size_t)(k0 + r) * 512 + o0 + c * 4);
    };
    auto loadB = [&](int buf, int k0) {
        for (int i = tid; i < 320; i += 256) {
            int r = i / 40, c = i % 40;
            cpa16(&Bs[buf][r * BROW + c * 4], g_muT + (k0 + r) * 160 + c * 4);
        }
    };
    loadA(0, 0); loadB(0, 0); cpa_commit();

    float4 acc[4][5];
    #pragma unroll
    for (int mt = 0; mt < 4; mt++)
        #pragma unroll
        for (int nt = 0; nt < 5; nt++) acc[mt][nt] = make_float4(0.f, 0.f, 0.f, 0.f);

    cpa_wait0();
    __syncthreads();

    for (int kc = 0; kc < 64; kc++) {
        int buf = kc & 1;
        if (kc < 63) { loadA(buf ^ 1, (kc + 1) * 8); loadB(buf ^ 1, (kc + 1) * 8); }
        cpa_commit();
        const float* ap = &As[buf][tig * AROW + warpM * 64 + gid];
        const float* bp = &Bs[buf][tig * BROW + warpN * 40 + gid];
        unsigned a[4][4];
        #pragma unroll
        for (int mt = 0; mt < 4; mt++) {
            const float* p0 = ap + mt * 16;
            a[mt][0] = __float_as_uint(p0[0]);
            a[mt][1] = __float_as_uint(p0[8]);
            a[mt][2] = __float_as_uint(p0[4 * AROW]);
            a[mt][3] = __float_as_uint(p0[4 * AROW + 8]);
        }
        #pragma unroll
        for (int nt = 0; nt < 5; nt++) {
            unsigned b0 = __float_as_uint(bp[nt * 8]);
            unsigned b1 = __float_as_uint(bp[nt * 8 + 4 * BROW]);
            #pragma unroll
            for (int mt = 0; mt < 4; mt++)
                mma_tf32(acc[mt][nt], a[mt], b0, b1);
        }
        cpa_wait0();
        __syncthreads();
    }

    #pragma unroll
    for (int mt = 0; mt < 4; mt++) {
        int m = o0 + warpM * 64 + mt * 16 + gid;
        #pragma unroll
        for (int nt = 0; nt < 5; nt++) {
            int n = warpN * 40 + nt * 8 + tig * 2;
            if (n < 152) {
                g_G[((size_t)(n * 25 + d)) * 512 + m] = acc[mt][nt].x;
                g_G[((size_t)(n * 25 + d)) * 512 + m + 8] = acc[mt][nt].z;
            }
            if (n + 1 < 152) {
                g_G[((size_t)((n + 1) * 25 + d)) * 512 + m] = acc[mt][nt].y;
                g_G[((size_t)((n + 1) * 25 + d)) * 512 + m + 8] = acc[mt][nt].w;
            }
        }
    }
}

// ---------------- fused gather (gavg) + actv -> apad2 direct ----------------
// grid: (NB*HH, 2) — each block handles a 32-px half-row for more parallelism.
__global__ void k_gact(const float* __restrict__ sh_b) {
    int bh = blockIdx.x;
    int b = bh >> 6, h = bh & 63;
    int w0 = blockIdx.y * 32;
    int tid = threadIdx.x;
    __shared__ int labw[5 * PD];
    for (int i = tid; i < 5 * PD; i += 256)
        labw[i] = g_labp[(b * PD + h + i / PD) * PD + (i % PD)];
    __syncthreads();
    float2 bias = ((const float2*)sh_b)[tid];
    unsigned* apadRow = g_apad2 + ((size_t)(b * 256 + tid) * PD + (h + 2)) * PD + 2;
    for (int w = w0; w < w0 + 32; w++) {
        float g0 = 0.f, g1 = 0.f, a0 = bias.x, a1 = bias.y;
        #pragma unroll
        for (int i = 0; i < 25; i++) {
            int j = labw[(i / 5) * PD + w + (i % 5)];
            if (j >= 0) {
                float2 gg = ((const float2*)(g_G + ((size_t)((b * LNC + j) * 25 + i)) * 512))[tid];
                unsigned wv = g_Wsh2[(j * 25 + i) * 256 + tid];
                g0 += gg.x; g1 += gg.y;
                a0 += __uint_as_float(wv << 16);
                a1 += __uint_as_float(wv & 0xffff0000u);
            }
        }
        ((float2*)(g_gavg + ((size_t)(b * PIX + h * WW + w)) * 512))[tid] = make_float2(g0, g1);
        apadRow[w] = bf16pack(fmaxf(a0, 0.f), fmaxf(a1, 0.f));
    }
}

// ---------------- spade conv via mma.sync bf16 m16n8k16 (R10/R13 config) ------
#define PLA   552
#define WROW  136
#define WTILE (8*WROW)
#define WKY   (5*WTILE)
#define ASBUF (8*PLA)
#define SMEMB ((2*ASBUF + 2*WKY)*4)

__global__ void __launch_bounds__(256, 1)
k_conv_mma(const float* __restrict__ sgb, const float* __restrict__ sbb) {
    extern __shared__ unsigned sm[];
    unsigned* Asm = sm;
    unsigned* Wsm = sm + 2 * ASBUF;

    const int o0 = blockIdx.x * 128;
    const int h0 = blockIdx.y * 4;
    const int b  = blockIdx.z;
    const int tid = threadIdx.x;
    const int lane = tid & 31, wid = tid >> 5;
    const int warpM = wid & 1;
    const int warpN = wid >> 1;
    const int tig = lane & 3, gid = lane >> 2;

    const unsigned* apadB = g_apad2 + (size_t)b * 256 * PD * PD;

    auto loadWs = [&](int r, int cp0, int ky) {
        #pragma unroll
        for (int ii = 0; ii < 5; ii++) {
            int i = ii * 256 + tid;
            int kx = i >> 8, rem = i & 255;
            int kc = rem >> 5, c4 = rem & 31;
            cpa16(Wsm + r * WKY + kx * WTILE + kc * WROW + c4 * 4,
                  g_Wsp2 + ((size_t)((cp0 + kc) * 25 + ky * 5 + kx)) * 512 + o0 + c4 * 4);
        }
    };
    auto loadAs = [&](int abf, int cp0) {
        for (int i = tid; i < 1088; i += 256) {
            int pl = i / 136, rem = i % 136;
            int row = rem / 17, c4 = rem % 17;
            cpa16(Asm + abf * ASBUF + pl * PLA + row * 68 + c4 * 4,
                  apadB + ((size_t)(cp0 + pl) * PD + (h0 + row)) * PD + c4 * 4);
        }
    };

    loadAs(0, 0);
    loadWs(0, 0, 0);
    cpa_commit();

    const int mrow = o0 + warpM * 64 + gid;
    float4 acc[4][8];
    #pragma unroll
    for (int mt = 0; mt < 4; mt++) {
        int r0 = mrow + mt * 16;
        float bx = (r0 < 256) ? sgb[r0] : sbb[r0 - 256];
        int r8 = r0 + 8;
        float bz = (r8 < 256) ? sgb[r8] : sbb[r8 - 256];
        #pragma unroll
        for (int nt = 0; nt < 8; nt++) acc[mt][nt] = make_float4(bx, bx, bz, bz);
    }

    cpa_wait0();
    __syncthreads();

    const int aoff = warpM * 64 + gid;

    for (int cc = 0; cc < 32; cc++) {
        int cp0 = cc * 8;
        int abuf = cc & 1;
        #pragma unroll 1
        for (int ky = 0; ky < 5; ky++) {
            int wbuf = (cc * 5 + ky) & 1;
            int kyn = ky + 1, ccn = cc, cp0n = cp0;
            if (kyn == 5) { kyn = 0; ccn = cc + 1; cp0n = cp0 + 8; }
            if (ccn < 32) {
                loadWs(wbuf ^ 1, cp0n, kyn);
                if (kyn == 0) loadAs(abuf ^ 1, cp0n);
            }
            cpa_commit();

            const unsigned* wk = Wsm + wbuf * WKY;
            const unsigned* bbase = Asm + abuf * ASBUF + tig * PLA
                                  + (warpN + ky) * 68 + gid;
            #pragma unroll
            for (int kx = 0; kx < 5; kx++) {
                unsigned a[4][4];
                #pragma unroll
                for (int mt = 0; mt < 4; mt++) {
                    const unsigned* p0 = wk + kx * WTILE + tig * WROW + aoff + mt * 16;
                    a[mt][0] = p0[0];
                    a[mt][1] = p0[8];
                    a[mt][2] = p0[4 * WROW];
                    a[mt][3] = p0[4 * WROW + 8];
                }
                const unsigned* bp = bbase + kx;
                #pragma unroll
                for (int nt = 0; nt < 8; nt++) {
                    unsigned b0 = bp[nt * 8];
                    unsigned b1 = bp[nt * 8 + 4 * PLA];
                    #pragma unroll
                    for (int mt = 0; mt < 4; mt++)
                        mma_bf16(acc[mt][nt], a[mt], b0, b1);
                }
            }
            cpa_wait0();
            __syncthreads();
        }
    }

    #pragma unroll
    for (int mt = 0; mt < 4; mt++) {
        int r0 = mrow + mt * 16;
        size_t base0 = (((size_t)b * 512 + r0) * HH + (h0 + warpN)) * WW;
        size_t base1 = (((size_t)b * 512 + r0 + 8) * HH + (h0 + warpN)) * WW;
        #pragma unroll
        for (int nt = 0; nt < 8; nt++) {
            int w = nt * 8 + tig * 2;
            *(float2*)&g_gsp[base0 + w] = make_float2(acc[mt][nt].x, acc[mt][nt].y);
            *(float2*)&g_gsp[base1 + w] = make_float2(acc[mt][nt].z, acc[mt][nt].w);
        }
    }
}

// ---------------- final blend (smem-transposed gavg reads) ----------------
__global__ void __launch_bounds__(256) k_final(const float* __restrict__ x,
                        const float* __restrict__ cgb, const float* __restrict__ cbb,
                        const float* __restrict__ bg, const float* __restrict__ bb,
                        float* __restrict__ out) {
    __shared__ float tsg[64][65];
    __shared__ float tsb[64][65];
    int bh = blockIdx.x;
    int b = bh >> 6, h = bh & 63;
    int tid = threadIdx.x;
    int w = tid & 63, os = tid >> 6;
    float ga = 1.f / (1.f + expf(-bg[0]));
    float ba = 1.f / (1.f + expf(-bb[0]));

    int lw0 = tid >> 4;
    int j4 = (tid & 15) * 4;

    for (int oc0 = 0; oc0 < 256; oc0 += 64) {
        float4 bg4 = *(const float4*)&cgb[oc0 + j4];
        float4 bb4 = *(const float4*)&cbb[oc0 + j4];
        #pragma unroll
        for (int it = 0; it < 4; it++) {
            int lw = lw0 + it * 16;
            size_t pbase = ((size_t)(b * PIX + h * WW + lw)) * 512;
            float4 vg = *(const float4*)&g_gavg[pbase + oc0 + j4];
            float4 vb = *(const float4*)&g_gavg[pbase + 256 + oc0 + j4];
            tsg[lw][j4 + 0] = vg.x + bg4.x;
            tsg[lw][j4 + 1] = vg.y + bg4.y;
            tsg[lw][j4 + 2] = vg.z + bg4.z;
            tsg[lw][j4 + 3] = vg.w + bg4.w;
            tsb[lw][j4 + 0] = vb.x + bb4.x;
            tsb[lw][j4 + 1] = vb.y + bb4.y;
            tsb[lw][j4 + 2] = vb.z + bb4.z;
            tsb[lw][j4 + 3] = vb.w + bb4.w;
        }
        __syncthreads();
        for (int oo = 0; oo < 64; oo += 4) {
            int o = oc0 + oo + os;
            float m = g_mean[b * NC + o], rs = g_rstd[b * NC + o];
            size_t xi = ((size_t)(b * NC + o) * HH + h) * WW + w;
            float nv = (x[xi] - m) * rs;
            float gs = g_gsp[((size_t)(b * 512 + o) * HH + h) * WW + w];
            float bs = g_gsp[((size_t)(b * 512 + o + 256) * HH + h) * WW + w];
            float gav = tsg[w][oo + os];
            float bav = tsb[w][oo + os];
            float gf = ga * gav + (1.f - ga) * gs;
            float bf = ba * bav + (1.f - ba) * bs;
            out[xi] = nv * (1.f + gf) + bf;
        }
        __syncthreads();
    }
}

// ---------------- launch ----------------
extern "C" void kernel_launch(void* const* d_in, const int* in_sizes, int n_in,
                              void* d_out, int out_size) {
    const float* x      = (const float*)d_in[0];
    const float* segmap = (const float*)d_in[1];
    const float* style  = (const float*)d_in[2];
    const float* fc_w   = (const float*)d_in[3];
    const float* fc_b   = (const float*)d_in[4];
    const float* cgw    = (const float*)d_in[5];
    const float* cgb    = (const float*)d_in[6];
    const float* cbw    = (const float*)d_in[7];
    const float* cbb    = (const float*)d_in[8];
    const float* ssw    = (const float*)d_in[9];
    const float* ssb    = (const float*)d_in[10];
    const float* sgw    = (const float*)d_in[11];
    const float* sgb    = (const float*)d_in[12];
    const float* sbw    = (const float*)d_in[13];
    const float* sbb    = (const float*)d_in[14];
    const float* bg     = (const float*)d_in[15];
    const float* bb     = (const float*)d_in[16];
    float* out = (float*)d_out;

    float* pWgbT; cudaGetSymbolAddress((void**)&pWgbT, g_WgbT);

    cudaFuncSetAttribute(k_conv_mma, cudaFuncAttributeMaxDynamicSharedMemorySize, SMEMB);

    dim3 tb(32, 8);

    k_stats<<<NB * NC, 256>>>(x);
    k_labels<<<(NB * PD * PD + 255) / 256, 256>>>(segmap);
    k_muTpad<<<16, 256>>>();
    k_mu<<<NB * LNC, 256>>>(style, fc_w, fc_b);

    k_wshpack<<<(475 * 256 + 255) / 256, 256>>>(ssw);
    k_wpackd<<<dim3(256, 8), tb>>>(sgw, 0);
    k_wpackd<<<dim3(256, 8), tb>>>(sbw, 256);
    k_transpose<<<dim3(400, 8), tb>>>(cgw, pWgbT, 256, 12800, 512, 0, 1, 1);
    k_transpose<<<dim3(400, 8), tb>>>(cbw, pWgbT, 256, 12800, 512, 256, 1, 1);

    k_G_mma<<<dim3(25, 4), 256>>>();
    k_gact<<<dim3(NB * HH, 2), 256>>>(ssb);
    k_conv_mma<<<dim3(4, 16, NB), 256, SMEMB>>>(sgb, sbb);
    k_final<<<NB * HH, 256>>>(x, cgb, cbb, bg, bb, out);
}

// round 17
// speedup vs baseline: 1.0847x; 1.0354x over previous
#include <cuda_runtime.h>
#include <math.h>

#define NB   8
#define NC   256
#define LNC  19
#define HH   64
#define WW   64
#define SL   512
#define PIX  (HH*WW)
#define PD   68

typedef unsigned long long ull;

// ---------------- scratch ----------------
static __device__ float    g_mean[NB*NC];
static __device__ float    g_rstd[NB*NC];
static __device__ int      g_labp[NB*PD*PD];
static __device__ float    g_mu[NB*LNC*SL];
static __device__ float    g_muT[512*160];           // [e][bj] tf32-rounded, padded
static __device__ unsigned g_Wsh2[475*256];          // [j*25+i][cpair] bf16x2
static __device__ unsigned g_Wsp2[6400*512];         // [cp*25+d][o2] bf16x2
static __device__ float    g_WgbT[12800*512];        // [d*512+e][o2] tf32-rounded
static __device__ float    g_G[NB*LNC*25*512];
static __device__ float    g_gavg[NB*PIX*512];       // [b][p][o2]
static __device__ unsigned g_apad2[NB*256*PD*PD];    // [b][cp][y][x] bf16x2; borders stay 0
static __device__ float    g_gsp[NB*512*PIX];        // biases included

// ---------------- helpers ----------------
__device__ __forceinline__ unsigned bf16pack(float lo, float hi) {
    unsigned r;
    asm("cvt.rn.bf16x2.f32 %0, %1, %2;" : "=r"(r) : "f"(hi), "f"(lo));
    return r;
}
__device__ __forceinline__ float tf32r(float x) {
    unsigned u; asm("cvt.rna.tf32.f32 %0, %1;" : "=r"(u) : "f"(x));
    return __uint_as_float(u);
}
__device__ __forceinline__ void mma_bf16(float4& d, const unsigned* a,
                                         unsigned b0, unsigned b1) {
    asm("mma.sync.aligned.m16n8k16.row.col.f32.bf16.bf16.f32 "
        "{%0,%1,%2,%3}, {%4,%5,%6,%7}, {%8,%9}, {%0,%1,%2,%3};"
        : "+f"(d.x), "+f"(d.y), "+f"(d.z), "+f"(d.w)
        : "r"(a[0]), "r"(a[1]), "r"(a[2]), "r"(a[3]), "r"(b0), "r"(b1));
}
__device__ __forceinline__ void mma_tf32(float4& d, const unsigned* a,
                                         unsigned b0, unsigned b1) {
    asm("mma.sync.aligned.m16n8k8.row.col.f32.tf32.tf32.f32 "
        "{%0,%1,%2,%3}, {%4,%5,%6,%7}, {%8,%9}, {%0,%1,%2,%3};"
        : "+f"(d.x), "+f"(d.y), "+f"(d.z), "+f"(d.w)
        : "r"(a[0]), "r"(a[1]), "r"(a[2]), "r"(a[3]), "r"(b0), "r"(b1));
}
__device__ __forceinline__ void cpa16(void* dst, const void* src) {
    unsigned s = (unsigned)__cvta_generic_to_shared(dst);
    asm volatile("cp.async.cg.shared.global [%0], [%1], 16;" :: "r"(s), "l"(src) : "memory");
}
__device__ __forceinline__ void cpa_commit() {
    asm volatile("cp.async.commit_group;" ::: "memory");
}
__device__ __forceinline__ void cpa_wait0() {
    asm volatile("cp.async.wait_group 0;" ::: "memory");
}

// ---------------- instance norm stats ----------------
__global__ void k_stats(const float* __restrict__ x) {
    int bc = blockIdx.x;
    const float* p = x + (size_t)bc * PIX;
    float s = 0.f, ss = 0.f;
    for (int i = threadIdx.x; i < PIX; i += 256) { float v = p[i]; s += v; ss += v * v; }
    __shared__ float sh[512];
    sh[threadIdx.x] = s; sh[256 + threadIdx.x] = ss; __syncthreads();
    for (int off = 128; off > 0; off >>= 1) {
        if (threadIdx.x < off) { sh[threadIdx.x] += sh[threadIdx.x + off]; sh[256 + threadIdx.x] += sh[256 + threadIdx.x + off]; }
        __syncthreads();
    }
    if (threadIdx.x == 0) {
        float m = sh[0] / (float)PIX;
        float v = sh[256] / (float)PIX - m * m;
        g_mean[bc] = m; g_rstd[bc] = rsqrtf(v + 1e-5f);
    }
}

// ---------------- padded label map ----------------
__global__ void k_labels(const float* __restrict__ segmap) {
    int idx = blockIdx.x * 256 + threadIdx.x;
    if (idx >= NB * PD * PD) return;
    int b = idx / (PD * PD), rem = idx % (PD * PD);
    int y = rem / PD, xx = rem % PD;
    int lab = -1;
    if (y >= 2 && y < 66 && xx >= 2 && xx < 66) {
        int h = y - 2, w = xx - 2;
        for (int j = LNC - 1; j >= 0; j--) {
            if (segmap[((b * LNC + j) * HH + h) * WW + w] > 0.f) { lab = j; break; }
        }
    }
    g_labp[idx] = lab;
}

// ---------------- mu (e-split 4-way; also writes tf32 muT) ----------------
__global__ void k_mu(const float* __restrict__ style, const float* __restrict__ fc_w,
                     const float* __restrict__ fc_b) {
    int bj = blockIdx.x;                 // 0..151
    int e0 = blockIdx.y * 128;           // e-chunk base
    int b = bj / LNC, j = bj % LNC;
    int tid = threadIdx.x, lane = tid & 31, wid = tid >> 5;
    __shared__ float sc[SL];
    for (int i = tid; i < SL; i += 256) sc[i] = style[(b * LNC + j) * SL + i];
    __syncthreads();
    for (int e = e0 + wid; e < e0 + 128; e += 8) {
        const float* row = fc_w + ((size_t)(j * SL + e)) * SL;
        float acc = 0.f;
        for (int d = lane; d < SL; d += 32) acc += sc[d] * row[d];
        for (int off = 16; off; off >>= 1) acc += __shfl_xor_sync(0xffffffffu, acc, off);
        if (lane == 0) {
            float v = fmaxf(acc + fc_b[j * SL + e], 0.f);
            g_mu[(b * LNC + j) * SL + e] = v;
            g_muT[e * 160 + bj] = tf32r(v);
        }
    }
}

// zero muT pad columns 152..159
__global__ void k_muTpad() {
    int idx = blockIdx.x * 256 + threadIdx.x;
    if (idx >= 512 * 8) return;
    g_muT[(idx >> 3) * 160 + 152 + (idx & 7)] = 0.f;
}

// ---------------- tiled transpose (optional tf32 rounding) ----------------
__global__ void k_transpose(const float* __restrict__ in, float* __restrict__ out,
                            int M, int N, int outStride, int colOff, int mode, int rnd) {
    __shared__ float t[32][33];
    int n0 = blockIdx.x * 32, m0 = blockIdx.y * 32;
    int tx = threadIdx.x, ty = threadIdx.y;
    for (int r = ty; r < 32; r += 8) {
        int m = m0 + r, n = n0 + tx;
        t[r][tx] = (m < M && n < N) ? in[(size_t)m * N + n] : 0.f;
    }
    __syncthreads();
    for (int r = ty; r < 32; r += 8) {
        int n = n0 + r, m = m0 + tx;
        if (n < N && m < M) {
            int orow = (mode == 1) ? (n % 25) * 512 + (n / 25) : n;
            float v = t[tx][r];
            if (rnd) v = tf32r(v);
            out[(size_t)orow * outStride + colOff + m] = v;
        }
    }
}

// ---------------- pack spade-shared weights into bf16x2 channel pairs ---------
__global__ void k_wshpack(const float* __restrict__ ssw) {
    int idx = blockIdx.x * 256 + threadIdx.x;
    if (idx >= 475 * 256) return;
    int row = idx >> 8, cp = idx & 255;
    g_Wsh2[idx] = bf16pack(ssw[(2 * cp) * 475 + row], ssw[(2 * cp + 1) * 475 + row]);
}

// ---------------- direct spade-weight transpose+pack ----------------
__global__ void k_wpackd(const float* __restrict__ src, int colOff) {
    __shared__ float t[50][33];
    int cp = blockIdx.x;
    int o0 = blockIdx.y * 32;
    int tx = threadIdx.x, ty = threadIdx.y;
    for (int r = ty; r < 32; r += 8) {
        const float* p = src + (size_t)(o0 + r) * 12800 + cp * 50;
        t[tx][r] = p[tx];
        if (tx < 18) t[32 + tx][r] = p[32 + tx];
    }
    __syncthreads();
    for (int d = ty; d < 25; d += 8) {
        g_Wsp2[(size_t)(cp * 25 + d) * 512 + colOff + o0 + tx] =
            bf16pack(t[d][tx], t[25 + d][tx]);
    }
}

// ---------------- k_G via tf32 MMA: per tap d, G[o2, bj] ----------------
#define AROW 136
#define BROW 168
__global__ void __launch_bounds__(256) k_G_mma() {
    __shared__ float As[2][8 * AROW];
    __shared__ float Bs[2][8 * BROW];
    int d = blockIdx.x, o0 = blockIdx.y * 128;
    int tid = threadIdx.x, lane = tid & 31, wid = tid >> 5;
    int warpM = wid & 1, warpN = wid >> 1;
    int tig = lane & 3, gid = lane >> 2;
    const float* Wd = g_WgbT + (size_t)d * 512 * 512;

    auto loadA = [&](int buf, int k0) {
        int r = tid >> 5, c = tid & 31;
        cpa16(&As[buf][r * AROW + c * 4], Wd + (size_t)(k0 + r) * 512 + o0 + c * 4);
    };
    auto loadB = [&](int buf, int k0) {
        for (int i = tid; i < 320; i += 256) {
            int r = i / 40, c = i % 40;
            cpa16(&Bs[buf][r * BROW + c * 4], g_muT + (k0 + r) * 160 + c * 4);
        }
    };
    loadA(0, 0); loadB(0, 0); cpa_commit();

    float4 acc[4][5];
    #pragma unroll
    for (int mt = 0; mt < 4; mt++)
        #pragma unroll
        for (int nt = 0; nt < 5; nt++) acc[mt][nt] = make_float4(0.f, 0.f, 0.f, 0.f);

    cpa_wait0();
    __syncthreads();

    for (int kc = 0; kc < 64; kc++) {
        int buf = kc & 1;
        if (kc < 63) { loadA(buf ^ 1, (kc + 1) * 8); loadB(buf ^ 1, (kc + 1) * 8); }
        cpa_commit();
        const float* ap = &As[buf][tig * AROW + warpM * 64 + gid];
        const float* bp = &Bs[buf][tig * BROW + warpN * 40 + gid];
        unsigned a[4][4];
        #pragma unroll
        for (int mt = 0; mt < 4; mt++) {
            const float* p0 = ap + mt * 16;
            a[mt][0] = __float_as_uint(p0[0]);
            a[mt][1] = __float_as_uint(p0[8]);
            a[mt][2] = __float_as_uint(p0[4 * AROW]);
            a[mt][3] = __float_as_uint(p0[4 * AROW + 8]);
        }
        #pragma unroll
        for (int nt = 0; nt < 5; nt++) {
            unsigned b0 = __float_as_uint(bp[nt * 8]);
            unsigned b1 = __float_as_uint(bp[nt * 8 + 4 * BROW]);
            #pragma unroll
            for (int mt = 0; mt < 4; mt++)
                mma_tf32(acc[mt][nt], a[mt], b0, b1);
        }
        cpa_wait0();
        __syncthreads();
    }

    #pragma unroll
    for (int mt = 0; mt < 4; mt++) {
        int m = o0 + warpM * 64 + mt * 16 + gid;
        #pragma unroll
        for (int nt = 0; nt < 5; nt++) {
            int n = warpN * 40 + nt * 8 + tig * 2;
            if (n < 152) {
                g_G[((size_t)(n * 25 + d)) * 512 + m] = acc[mt][nt].x;
                g_G[((size_t)(n * 25 + d)) * 512 + m + 8] = acc[mt][nt].z;
            }
            if (n + 1 < 152) {
                g_G[((size_t)((n + 1) * 25 + d)) * 512 + m] = acc[mt][nt].y;
                g_G[((size_t)((n + 1) * 25 + d)) * 512 + m + 8] = acc[mt][nt].w;
            }
        }
    }
}

// ---------------- fused gather (gavg) + actv -> apad2 direct ----------------
__global__ void k_gact(const float* __restrict__ sh_b) {
    int bh = blockIdx.x;
    int b = bh >> 6, h = bh & 63;
    int w0 = blockIdx.y * 32;
    int tid = threadIdx.x;
    __shared__ int labw[5 * PD];
    for (int i = tid; i < 5 * PD; i += 256)
        labw[i] = g_labp[(b * PD + h + i / PD) * PD + (i % PD)];
    __syncthreads();
    float2 bias = ((const float2*)sh_b)[tid];
    unsigned* apadRow = g_apad2 + ((size_t)(b * 256 + tid) * PD + (h + 2)) * PD + 2;
    for (int w = w0; w < w0 + 32; w++) {
        float g0 = 0.f, g1 = 0.f, a0 = bias.x, a1 = bias.y;
        #pragma unroll
        for (int i = 0; i < 25; i++) {
            int j = labw[(i / 5) * PD + w + (i % 5)];
            if (j >= 0) {
                float2 gg = ((const float2*)(g_G + ((size_t)((b * LNC + j) * 25 + i)) * 512))[tid];
                unsigned wv = g_Wsh2[(j * 25 + i) * 256 + tid];
                g0 += gg.x; g1 += gg.y;
                a0 += __uint_as_float(wv << 16);
                a1 += __uint_as_float(wv & 0xffff0000u);
            }
        }
        ((float2*)(g_gavg + ((size_t)(b * PIX + h * WW + w)) * 512))[tid] = make_float2(g0, g1);
        apadRow[w] = bf16pack(fmaxf(a0, 0.f), fmaxf(a1, 0.f));
    }
}

// ---------------- spade conv via mma.sync bf16 m16n8k16 (R10/R13 config) ------
#define PLA   552
#define WROW  136
#define WTILE (8*WROW)
#define WKY   (5*WTILE)
#define ASBUF (8*PLA)
#define SMEMB ((2*ASBUF + 2*WKY)*4)

__global__ void __launch_bounds__(256, 1)
k_conv_mma(const float* __restrict__ sgb, const float* __restrict__ sbb) {
    extern __shared__ unsigned sm[];
    unsigned* Asm = sm;
    unsigned* Wsm = sm + 2 * ASBUF;

    const int o0 = blockIdx.x * 128;
    const int h0 = blockIdx.y * 4;
    const int b  = blockIdx.z;
    const int tid = threadIdx.x;
    const int lane = tid & 31, wid = tid >> 5;
    const int warpM = wid & 1;
    const int warpN = wid >> 1;
    const int tig = lane & 3, gid = lane >> 2;

    const unsigned* apadB = g_apad2 + (size_t)b * 256 * PD * PD;

    auto loadWs = [&](int r, int cp0, int ky) {
        #pragma unroll
        for (int ii = 0; ii < 5; ii++) {
            int i = ii * 256 + tid;
            int kx = i >> 8, rem = i & 255;
            int kc = rem >> 5, c4 = rem & 31;
            cpa16(Wsm + r * WKY + kx * WTILE + kc * WROW + c4 * 4,
                  g_Wsp2 + ((size_t)((cp0 + kc) * 25 + ky * 5 + kx)) * 512 + o0 + c4 * 4);
        }
    };
    auto loadAs = [&](int abf, int cp0) {
        for (int i = tid; i < 1088; i += 256) {
            int pl = i / 136, rem = i % 136;
            int row = rem / 17, c4 = rem % 17;
            cpa16(Asm + abf * ASBUF + pl * PLA + row * 68 + c4 * 4,
                  apadB + ((size_t)(cp0 + pl) * PD + (h0 + row)) * PD + c4 * 4);
        }
    };

    loadAs(0, 0);
    loadWs(0, 0, 0);
    cpa_commit();

    const int mrow = o0 + warpM * 64 + gid;
    float4 acc[4][8];
    #pragma unroll
    for (int mt = 0; mt < 4; mt++) {
        int r0 = mrow + mt * 16;
        float bx = (r0 < 256) ? sgb[r0] : sbb[r0 - 256];
        int r8 = r0 + 8;
        float bz = (r8 < 256) ? sgb[r8] : sbb[r8 - 256];
        #pragma unroll
        for (int nt = 0; nt < 8; nt++) acc[mt][nt] = make_float4(bx, bx, bz, bz);
    }

    cpa_wait0();
    __syncthreads();

    const int aoff = warpM * 64 + gid;

    for (int cc = 0; cc < 32; cc++) {
        int cp0 = cc * 8;
        int abuf = cc & 1;
        #pragma unroll 1
        for (int ky = 0; ky < 5; ky++) {
            int wbuf = (cc * 5 + ky) & 1;
            int kyn = ky + 1, ccn = cc, cp0n = cp0;
            if (kyn == 5) { kyn = 0; ccn = cc + 1; cp0n = cp0 + 8; }
            if (ccn < 32) {
                loadWs(wbuf ^ 1, cp0n, kyn);
                if (kyn == 0) loadAs(abuf ^ 1, cp0n);
            }
            cpa_commit();

            const unsigned* wk = Wsm + wbuf * WKY;
            const unsigned* bbase = Asm + abuf * ASBUF + tig * PLA
                                  + (warpN + ky) * 68 + gid;
            #pragma unroll
            for (int kx = 0; kx < 5; kx++) {
                unsigned a[4][4];
                #pragma unroll
                for (int mt = 0; mt < 4; mt++) {
                    const unsigned* p0 = wk + kx * WTILE + tig * WROW + aoff + mt * 16;
                    a[mt][0] = p0[0];
                    a[mt][1] = p0[8];
                    a[mt][2] = p0[4 * WROW];
                    a[mt][3] = p0[4 * WROW + 8];
                }
                const unsigned* bp = bbase + kx;
                #pragma unroll
                for (int nt = 0; nt < 8; nt++) {
                    unsigned b0 = bp[nt * 8];
                    unsigned b1 = bp[nt * 8 + 4 * PLA];
                    #pragma unroll
                    for (int mt = 0; mt < 4; mt++)
                        mma_bf16(acc[mt][nt], a[mt], b0, b1);
                }
            }
            cpa_wait0();
            __syncthreads();
        }
    }

    #pragma unroll
    for (int mt = 0; mt < 4; mt++) {
        int r0 = mrow + mt * 16;
        size_t base0 = (((size_t)b * 512 + r0) * HH + (h0 + warpN)) * WW;
        size_t base1 = (((size_t)b * 512 + r0 + 8) * HH + (h0 + warpN)) * WW;
        #pragma unroll
        for (int nt = 0; nt < 8; nt++) {
            int w = nt * 8 + tig * 2;
            *(float2*)&g_gsp[base0 + w] = make_float2(acc[mt][nt].x, acc[mt][nt].y);
            *(float2*)&g_gsp[base1 + w] = make_float2(acc[mt][nt].z, acc[mt][nt].w);
        }
    }
}

// ---------------- final blend (smem-transposed gavg reads) ----------------
__global__ void __launch_bounds__(256) k_final(const float* __restrict__ x,
                        const float* __restrict__ cgb, const float* __restrict__ cbb,
                        const float* __restrict__ bg, const float* __restrict__ bb,
                        float* __restrict__ out) {
    __shared__ float tsg[64][65];
    __shared__ float tsb[64][65];
    int bh = blockIdx.x;
    int b = bh >> 6, h = bh & 63;
    int tid = threadIdx.x;
    int w = tid & 63, os = tid >> 6;
    float ga = 1.f / (1.f + expf(-bg[0]));
    float ba = 1.f / (1.f + expf(-bb[0]));

    int lw0 = tid >> 4;
    int j4 = (tid & 15) * 4;

    for (int oc0 = 0; oc0 < 256; oc0 += 64) {
        float4 bg4 = *(const float4*)&cgb[oc0 + j4];
        float4 bb4 = *(const float4*)&cbb[oc0 + j4];
        #pragma unroll
        for (int it = 0; it < 4; it++) {
            int lw = lw0 + it * 16;
            size_t pbase = ((size_t)(b * PIX + h * WW + lw)) * 512;
            float4 vg = *(const float4*)&g_gavg[pbase + oc0 + j4];
            float4 vb = *(const float4*)&g_gavg[pbase + 256 + oc0 + j4];
            tsg[lw][j4 + 0] = vg.x + bg4.x;
            tsg[lw][j4 + 1] = vg.y + bg4.y;
            tsg[lw][j4 + 2] = vg.z + bg4.z;
            tsg[lw][j4 + 3] = vg.w + bg4.w;
            tsb[lw][j4 + 0] = vb.x + bb4.x;
            tsb[lw][j4 + 1] = vb.y + bb4.y;
            tsb[lw][j4 + 2] = vb.z + bb4.z;
            tsb[lw][j4 + 3] = vb.w + bb4.w;
        }
        __syncthreads();
        for (int oo = 0; oo < 64; oo += 4) {
            int o = oc0 + oo + os;
            float m = g_mean[b * NC + o], rs = g_rstd[b * NC + o];
            size_t xi = ((size_t)(b * NC + o) * HH + h) * WW + w;
            float nv = (x[xi] - m) * rs;
            float gs = g_gsp[((size_t)(b * 512 + o) * HH + h) * WW + w];
            float bs = g_gsp[((size_t)(b * 512 + o + 256) * HH + h) * WW + w];
            float gav = tsg[w][oo + os];
            float bav = tsb[w][oo + os];
            float gf = ga * gav + (1.f - ga) * gs;
            float bf = ba * bav + (1.f - ba) * bs;
            out[xi] = nv * (1.f + gf) + bf;
        }
        __syncthreads();
    }
}

// ---------------- launch ----------------
extern "C" void kernel_launch(void* const* d_in, const int* in_sizes, int n_in,
                              void* d_out, int out_size) {
    const float* x      = (const float*)d_in[0];
    const float* segmap = (const float*)d_in[1];
    const float* style  = (const float*)d_in[2];
    const float* fc_w   = (const float*)d_in[3];
    const float* fc_b   = (const float*)d_in[4];
    const float* cgw    = (const float*)d_in[5];
    const float* cgb    = (const float*)d_in[6];
    const float* cbw    = (const float*)d_in[7];
    const float* cbb    = (const float*)d_in[8];
    const float* ssw    = (const float*)d_in[9];
    const float* ssb    = (const float*)d_in[10];
    const float* sgw    = (const float*)d_in[11];
    const float* sgb    = (const float*)d_in[12];
    const float* sbw    = (const float*)d_in[13];
    const float* sbb    = (const float*)d_in[14];
    const float* bg     = (const float*)d_in[15];
    const float* bb     = (const float*)d_in[16];
    float* out = (float*)d_out;

    float* pWgbT; cudaGetSymbolAddress((void**)&pWgbT, g_WgbT);

    cudaFuncSetAttribute(k_conv_mma, cudaFuncAttributeMaxDynamicSharedMemorySize, SMEMB);

    dim3 tb(32, 8);

    k_stats<<<NB * NC, 256>>>(x);
    k_labels<<<(NB * PD * PD + 255) / 256, 256>>>(segmap);
    k_muTpad<<<16, 256>>>();
    k_mu<<<dim3(NB * LNC, 4), 256>>>(style, fc_w, fc_b);

    k_wshpack<<<(475 * 256 + 255) / 256, 256>>>(ssw);
    k_wpackd<<<dim3(256, 8), tb>>>(sgw, 0);
    k_wpackd<<<dim3(256, 8), tb>>>(sbw, 256);
    k_transpose<<<dim3(400, 8), tb>>>(cgw, pWgbT, 256, 12800, 512, 0, 1, 1);
    k_transpose<<<dim3(400, 8), tb>>>(cbw, pWgbT, 256, 12800, 512, 256, 1, 1);

    k_G_mma<<<dim3(25, 4), 256>>>();
    k_gact<<<dim3(NB * HH, 2), 256>>>(ssb);
    k_conv_mma<<<dim3(4, 16, NB), 256, SMEMB>>>(sgb, sbb);
    k_final<<<NB * HH, 256>>>(x, cgb, cbb, bg, bb, out);
}